// round 1
// baseline (speedup 1.0000x reference)
#include <cuda_runtime.h>
#include <math.h>
#include <stdint.h>

// Problem constants
#define BB   128     // batch
#define TT   1024    // seq
#define DD   128     // in_dim
#define UU   256     // units
#define GG   768     // 3*units (r|u|c)
#define KK3  384     // 3*in_dim (x_t | x_{t-1} | x_{t-2})

// Scratch (device globals: no allocations allowed)
__device__ float g_W3[KK3 * GG];                 // combined input weights [k3][j]
__device__ float g_Pre[(size_t)BB * TT * GG];    // per-step input pre-activations (402 MB)

// ---------------------------------------------------------------------------
// Kernel 1: build combined input-projection weights.
// input_weight layout: (128, 7*256) row-major, blocks:
//   [Wxr, Wxu, Wxh, dWxr, dWxu, ddWxr, ddWxu]
// Gate pre-act = x_t@Wg + (x_t - x_{t-1})@dWg + (x_t - 2x_{t-1} + x_{t-2})@ddWg
//   => coeff(x_t)     =  Wg + dWg + ddWg
//      coeff(x_{t-1}) = -(dWg + 2 ddWg)
//      coeff(x_{t-2}) =  ddWg
// cand uses only x_t@Wxh.
// ---------------------------------------------------------------------------
__global__ void combine_kernel(const float* __restrict__ iw) {
    int idx = blockIdx.x * blockDim.x + threadIdx.x;
    if (idx >= KK3 * GG) return;
    int k3   = idx / GG;        // 0..383
    int j    = idx - k3 * GG;   // 0..767
    int gate = j >> 8;          // 0=r, 1=u, 2=c
    int ju   = j & 255;
    int s    = k3 >> 7;         // time shift 0,1,2
    int k    = k3 & 127;
    const float* row = iw + (size_t)k * (7 * UU);
    float v = 0.f;
    if (gate == 0) {
        float W = row[0 * UU + ju], dW = row[3 * UU + ju], ddW = row[5 * UU + ju];
        v = (s == 0) ? (W + dW + ddW) : (s == 1) ? -(dW + 2.f * ddW) : ddW;
    } else if (gate == 1) {
        float W = row[1 * UU + ju], dW = row[4 * UU + ju], ddW = row[6 * UU + ju];
        v = (s == 0) ? (W + dW + ddW) : (s == 1) ? -(dW + 2.f * ddW) : ddW;
    } else {
        v = (s == 0) ? row[2 * UU + ju] : 0.f;
    }
    g_W3[idx] = v;
}

// ---------------------------------------------------------------------------
// Kernel 2: Pre[m][j] = sum_k3 X3[m][k3] * W3[k3][j] + bias[j]
// where m = b*1024 + t and X3 is x shifted by s=k3>>7 steps (0 before t=s).
// Classic 128x128 register-tiled SGEMM, 256 threads, 8x8 microtile, BK=8,
// software-prefetched gmem loads. Column blocks >= 512 (cand) only need K=128.
// ---------------------------------------------------------------------------
__global__ void __launch_bounds__(256, 2) pre_gemm_kernel(const float* __restrict__ x,
                                                          const float* __restrict__ bias) {
    __shared__ float As[8][128];
    __shared__ float Bs[8][128];

    const int tid = threadIdx.x;
    const int m0  = blockIdx.x * 128;
    const int n0  = blockIdx.y * 128;
    const int kmax = (n0 >= 512) ? 128 : KK3;

    const int tx = tid & 15;
    const int ty = tid >> 4;

    // loader mapping
    const int lr  = tid >> 1;          // A row 0..127
    const int lk  = (tid & 1) << 2;    // A k sub-offset 0 or 4
    const int lkb = tid >> 5;          // B k 0..7
    const int ljb = (tid & 31) << 2;   // B col offset

    const int m    = m0 + lr;
    const int tmod = m & (TT - 1);

    float acc[8][8];
#pragma unroll
    for (int i = 0; i < 8; i++)
#pragma unroll
        for (int j = 0; j < 8; j++) acc[i][j] = 0.f;

    // prologue loads (k0 = 0, shift s = 0: always valid)
    float4 a4 = *reinterpret_cast<const float4*>(x + (size_t)m * DD + lk);
    float4 b4 = *reinterpret_cast<const float4*>(g_W3 + (size_t)lkb * GG + n0 + ljb);

    for (int k0 = 0; k0 < kmax; k0 += 8) {
        __syncthreads();
        As[lk + 0][lr] = a4.x;
        As[lk + 1][lr] = a4.y;
        As[lk + 2][lr] = a4.z;
        As[lk + 3][lr] = a4.w;
        *reinterpret_cast<float4*>(&Bs[lkb][ljb]) = b4;
        __syncthreads();

        // prefetch next tile while computing
        int k0n = k0 + 8;
        if (k0n < kmax) {
            int s  = k0n >> 7;                 // time shift for this K segment
            int kk = (k0n & 127) + lk;
            if (tmod >= s)
                a4 = *reinterpret_cast<const float4*>(x + (size_t)(m - s) * DD + kk);
            else
                a4 = make_float4(0.f, 0.f, 0.f, 0.f);
            b4 = *reinterpret_cast<const float4*>(g_W3 + (size_t)(k0n + lkb) * GG + n0 + ljb);
        }

#pragma unroll
        for (int k = 0; k < 8; k++) {
            float4 af0 = *reinterpret_cast<const float4*>(&As[k][ty * 8]);
            float4 af1 = *reinterpret_cast<const float4*>(&As[k][ty * 8 + 4]);
            float4 bf0 = *reinterpret_cast<const float4*>(&Bs[k][tx * 8]);
            float4 bf1 = *reinterpret_cast<const float4*>(&Bs[k][tx * 8 + 4]);
            float a_[8] = {af0.x, af0.y, af0.z, af0.w, af1.x, af1.y, af1.z, af1.w};
            float b_[8] = {bf0.x, bf0.y, bf0.z, bf0.w, bf1.x, bf1.y, bf1.z, bf1.w};
#pragma unroll
            for (int i = 0; i < 8; i++)
#pragma unroll
                for (int j = 0; j < 8; j++) acc[i][j] += a_[i] * b_[j];
        }
    }

#pragma unroll
    for (int i = 0; i < 8; i++) {
        size_t rowoff = (size_t)(m0 + ty * 8 + i) * GG + n0 + tx * 8;
#pragma unroll
        for (int j = 0; j < 8; j += 4) {
            float4 v;
            v.x = acc[i][j + 0] + bias[n0 + tx * 8 + j + 0];
            v.y = acc[i][j + 1] + bias[n0 + tx * 8 + j + 1];
            v.z = acc[i][j + 2] + bias[n0 + tx * 8 + j + 2];
            v.w = acc[i][j + 3] + bias[n0 + tx * 8 + j + 3];
            *reinterpret_cast<float4*>(&g_Pre[rowoff + j]) = v;
        }
    }
}

// ---------------------------------------------------------------------------
// Kernel 3: recurrence. Batch rows are independent -> 64 CTAs x 2 rows each,
// persistent over all 1024 steps. Weights streamed from L2 (768 KB fp32 / step
// / CTA). 512 threads: thread = (K-quarter kq, col-group cg). Each thread
// accumulates 4 gate columns x 2 rows over its 64-k slice; cross-K reduction
// through SMEM; gate nonlinearities; then the cand GEMM the same way.
//   hidden_weight layout (256, 768): cols [0,256)=Whr, [256,512)=Whu,
//   [512,768)=Whh -- matches g_Pre column layout.
// ---------------------------------------------------------------------------
__global__ void __launch_bounds__(512, 1) rnn_kernel(const float* __restrict__ Wh,
                                                     float* __restrict__ out) {
    __shared__ float sh_h[2][UU];
    __shared__ float sh_rh[2][UU];
    __shared__ float sh_u[2][UU];
    __shared__ float sh_red[4 * 2 * 512];   // 16 KB reduction scratch

    const int tid = threadIdx.x;            // 0..511
    const int b0  = blockIdx.x * 2;

    for (int i = tid; i < 2 * UU; i += 512) ((float*)sh_h)[i] = 0.f;
    __syncthreads();

    const int kq = tid >> 7;       // K quarter (64 k's each)
    const int cg = tid & 127;
    const int c0 = cg * 4;         // phase-1 columns (r|u space, 0..511)
    const int c2 = cg * 2;         // phase-2 columns (cand space, 0..255)

    const float* pre0 = g_Pre + (size_t)b0 * TT * GG;
    const float* pre1 = g_Pre + (size_t)(b0 + 1) * TT * GG;

    for (int t = 0; t < TT; t++) {
        // ---- phase 1: partial h @ [Whr|Whu] over this K-quarter ----
        float a00 = 0.f, a01 = 0.f, a02 = 0.f, a03 = 0.f;
        float a10 = 0.f, a11 = 0.f, a12 = 0.f, a13 = 0.f;
        {
            const float* wp = Wh + (size_t)(kq * 64) * GG + c0;
            const float* hp0 = &sh_h[0][kq * 64];
            const float* hp1 = &sh_h[1][kq * 64];
#pragma unroll 4
            for (int k = 0; k < 64; k++) {
                float4 w = *reinterpret_cast<const float4*>(wp);
                wp += GG;
                float h0 = hp0[k];
                float h1 = hp1[k];
                a00 += h0 * w.x; a01 += h0 * w.y; a02 += h0 * w.z; a03 += h0 * w.w;
                a10 += h1 * w.x; a11 += h1 * w.y; a12 += h1 * w.z; a13 += h1 * w.w;
            }
        }
        {
            float* rp = sh_red + kq * 1024;
            *reinterpret_cast<float4*>(&rp[0 * 512 + c0]) = make_float4(a00, a01, a02, a03);
            *reinterpret_cast<float4*>(&rp[1 * 512 + c0]) = make_float4(a10, a11, a12, a13);
        }
        __syncthreads();

        // ---- finalize gates r, u ----
#pragma unroll
        for (int it = 0; it < 2; it++) {
            int item = tid + it * 512;          // 0..1023
            int r = item >> 9;
            int j = item & 511;
            float v = sh_red[0 * 1024 + r * 512 + j] + sh_red[1 * 1024 + r * 512 + j] +
                      sh_red[2 * 1024 + r * 512 + j] + sh_red[3 * 1024 + r * 512 + j];
            v += (r ? pre1 : pre0)[(size_t)t * GG + j];
            float sg = 1.f / (1.f + expf(-v));
            if (j < 256) sh_rh[r][j] = sg * sh_h[r][j];
            else         sh_u[r][j - 256] = sg;
        }
        __syncthreads();

        // ---- phase 2: partial (r*h) @ Whh over this K-quarter ----
        float b00 = 0.f, b01 = 0.f, b10 = 0.f, b11 = 0.f;
        {
            const float* wp = Wh + (size_t)(kq * 64) * GG + 512 + c2;
            const float* rp0 = &sh_rh[0][kq * 64];
            const float* rp1 = &sh_rh[1][kq * 64];
#pragma unroll 4
            for (int k = 0; k < 64; k++) {
                float2 w = *reinterpret_cast<const float2*>(wp);
                wp += GG;
                float r0 = rp0[k];
                float r1 = rp1[k];
                b00 += r0 * w.x; b01 += r0 * w.y;
                b10 += r1 * w.x; b11 += r1 * w.y;
            }
        }
        {
            float* rp = sh_red + kq * 512;
            *reinterpret_cast<float2*>(&rp[0 * 256 + c2]) = make_float2(b00, b01);
            *reinterpret_cast<float2*>(&rp[1 * 256 + c2]) = make_float2(b10, b11);
        }
        __syncthreads();

        // ---- finalize cand + state update + output ----
        {
            int r = tid >> 8;
            int j = tid & 255;
            float v = sh_red[0 * 512 + r * 256 + j] + sh_red[1 * 512 + r * 256 + j] +
                      sh_red[2 * 512 + r * 256 + j] + sh_red[3 * 512 + r * 256 + j];
            v += (r ? pre1 : pre0)[(size_t)t * GG + 512 + j];
            float c = tanhf(v);
            float u = sh_u[r][j];
            float hn = u * sh_h[r][j] + (1.f - u) * c;
            sh_h[r][j] = hn;   // same thread read+write of this element: safe
            out[((size_t)(b0 + r) * TT + t) * UU + j] = hn;
        }
        __syncthreads();
    }
}

// ---------------------------------------------------------------------------
// Launch
// inputs: [0]=x (128,1024,128) f32, [1]=input_weight (128,1792) f32,
//         [2]=hidden_weight (256,768) f32, [3]=bias (768) f32,
//         [4]=constant (256,128) f32 (structurally [I;0] -> folded analytically)
// output: (128,1024,256) f32
// ---------------------------------------------------------------------------
extern "C" void kernel_launch(void* const* d_in, const int* in_sizes, int n_in,
                              void* d_out, int out_size) {
    const float* x    = (const float*)d_in[0];
    const float* iw   = (const float*)d_in[1];
    const float* hw   = (const float*)d_in[2];
    const float* bias = (const float*)d_in[3];
    float* out = (float*)d_out;

    combine_kernel<<<(KK3 * GG + 1023) / 1024, 1024>>>(iw);

    dim3 pgrid(BB * TT / 128, GG / 128);   // 1024 x 6
    pre_gemm_kernel<<<pgrid, 256>>>(x, bias);

    rnn_kernel<<<BB / 2, 512>>>(hw, out);
}

// round 3
// speedup vs baseline: 1.6468x; 1.6468x over previous
#include <cuda_runtime.h>
#include <math.h>
#include <stdint.h>

// Problem constants
#define BB   128     // batch
#define TT   1024    // seq
#define DD   128     // in_dim
#define UU   256     // units
#define GG   768     // 3*units (r|u|c)
#define KK3  384     // 3*in_dim (x_t | x_{t-1} | x_{t-2})

// Packed fp32x2 FMA (SASS FFMA2) — only reachable via PTX
#define FMA2(acc, a, b) asm("fma.rn.f32x2 %0, %1, %2, %0;" : "+l"(acc) : "l"(a), "l"(b))
#define PACK2(d, lo, hi) asm("mov.b64 %0, {%1, %2};" : "=l"(d) : "f"(lo), "f"(hi))
#define UNPK2(lo, hi, v) asm("mov.b64 {%0, %1}, %2;" : "=f"(lo), "=f"(hi) : "l"(v))

#define CLUSTER_SYNC() do { \
    asm volatile("barrier.cluster.arrive.aligned;" ::: "memory"); \
    asm volatile("barrier.cluster.wait.aligned;" ::: "memory"); \
} while (0)

__device__ __forceinline__ void dsmem_store(uint32_t saddr, uint32_t rank, float v) {
    uint32_t remote;
    asm("mapa.shared::cluster.u32 %0, %1, %2;" : "=r"(remote) : "r"(saddr), "r"(rank));
    asm volatile("st.shared::cluster.f32 [%0], %1;" :: "r"(remote), "f"(v) : "memory");
}

// Scratch (device globals: no allocations allowed)
__device__ float g_W3[KK3 * GG];                 // combined input weights [k3][j]
__device__ float g_Pre[(size_t)BB * TT * GG];    // per-step input pre-activations (402 MB)

// ---------------------------------------------------------------------------
// Kernel 1: build combined input-projection weights (see round-0 derivation).
// ---------------------------------------------------------------------------
__global__ void combine_kernel(const float* __restrict__ iw) {
    int idx = blockIdx.x * blockDim.x + threadIdx.x;
    if (idx >= KK3 * GG) return;
    int k3   = idx / GG;
    int j    = idx - k3 * GG;
    int gate = j >> 8;
    int ju   = j & 255;
    int s    = k3 >> 7;
    int k    = k3 & 127;
    const float* row = iw + (size_t)k * (7 * UU);
    float v = 0.f;
    if (gate == 0) {
        float W = row[0 * UU + ju], dW = row[3 * UU + ju], ddW = row[5 * UU + ju];
        v = (s == 0) ? (W + dW + ddW) : (s == 1) ? -(dW + 2.f * ddW) : ddW;
    } else if (gate == 1) {
        float W = row[1 * UU + ju], dW = row[4 * UU + ju], ddW = row[6 * UU + ju];
        v = (s == 0) ? (W + dW + ddW) : (s == 1) ? -(dW + 2.f * ddW) : ddW;
    } else {
        v = (s == 0) ? row[2 * UU + ju] : 0.f;
    }
    g_W3[idx] = v;
}

// ---------------------------------------------------------------------------
// Kernel 2: Pre[m][j] = sum_k3 X3[m][k3] * W3[k3][j] + bias[j]
// 128x128 register-tiled SGEMM with packed f32x2 FMA (FFMA2).
// ---------------------------------------------------------------------------
__global__ void __launch_bounds__(256, 2) pre_gemm_kernel(const float* __restrict__ x,
                                                          const float* __restrict__ bias) {
    __shared__ float As[8][128];
    __shared__ float Bs[8][128];

    const int tid = threadIdx.x;
    const int m0  = blockIdx.x * 128;
    const int n0  = blockIdx.y * 128;
    const int kmax = (n0 >= 512) ? 128 : KK3;

    const int tx = tid & 15;
    const int ty = tid >> 4;

    const int lr  = tid >> 1;
    const int lk  = (tid & 1) << 2;
    const int lkb = tid >> 5;
    const int ljb = (tid & 31) << 2;

    const int m    = m0 + lr;
    const int tmod = m & (TT - 1);

    unsigned long long acc2[8][4];
#pragma unroll
    for (int i = 0; i < 8; i++)
#pragma unroll
        for (int j = 0; j < 4; j++) acc2[i][j] = 0ull;

    float4 a4 = *reinterpret_cast<const float4*>(x + (size_t)m * DD + lk);
    float4 b4 = *reinterpret_cast<const float4*>(g_W3 + (size_t)lkb * GG + n0 + ljb);

    for (int k0 = 0; k0 < kmax; k0 += 8) {
        __syncthreads();
        As[lk + 0][lr] = a4.x;
        As[lk + 1][lr] = a4.y;
        As[lk + 2][lr] = a4.z;
        As[lk + 3][lr] = a4.w;
        *reinterpret_cast<float4*>(&Bs[lkb][ljb]) = b4;
        __syncthreads();

        int k0n = k0 + 8;
        if (k0n < kmax) {
            int s  = k0n >> 7;
            int kk = (k0n & 127) + lk;
            if (tmod >= s)
                a4 = *reinterpret_cast<const float4*>(x + (size_t)(m - s) * DD + kk);
            else
                a4 = make_float4(0.f, 0.f, 0.f, 0.f);
            b4 = *reinterpret_cast<const float4*>(g_W3 + (size_t)(k0n + lkb) * GG + n0 + ljb);
        }

#pragma unroll
        for (int k = 0; k < 8; k++) {
            float4 af0 = *reinterpret_cast<const float4*>(&As[k][ty * 8]);
            float4 af1 = *reinterpret_cast<const float4*>(&As[k][ty * 8 + 4]);
            ulonglong2 bb0 = *reinterpret_cast<const ulonglong2*>(&Bs[k][tx * 8]);
            ulonglong2 bb1 = *reinterpret_cast<const ulonglong2*>(&Bs[k][tx * 8 + 4]);
            unsigned long long b2[4] = {bb0.x, bb0.y, bb1.x, bb1.y};
            float a_[8] = {af0.x, af0.y, af0.z, af0.w, af1.x, af1.y, af1.z, af1.w};
#pragma unroll
            for (int i = 0; i < 8; i++) {
                unsigned long long a2;
                PACK2(a2, a_[i], a_[i]);
#pragma unroll
                for (int jp = 0; jp < 4; jp++) FMA2(acc2[i][jp], a2, b2[jp]);
            }
        }
    }

#pragma unroll
    for (int i = 0; i < 8; i++) {
        size_t rowoff = (size_t)(m0 + ty * 8 + i) * GG + n0 + tx * 8;
#pragma unroll
        for (int jp = 0; jp < 4; jp += 2) {
            float4 v;
            UNPK2(v.x, v.y, acc2[i][jp]);
            UNPK2(v.z, v.w, acc2[i][jp + 1]);
            int jb = jp * 2;
            v.x += bias[n0 + tx * 8 + jb + 0];
            v.y += bias[n0 + tx * 8 + jb + 1];
            v.z += bias[n0 + tx * 8 + jb + 2];
            v.w += bias[n0 + tx * 8 + jb + 3];
            *reinterpret_cast<float4*>(&g_Pre[rowoff + jb]) = v;
        }
    }
}

// ---------------------------------------------------------------------------
// Kernel 3: recurrence with SMEM-resident weights.
// 32 clusters x 4 CTAs (grid = 128 CTAs!); each cluster owns 4 batch rows;
// each CTA (rank cr) owns output columns [cr*64, cr*64+64) of each gate and
// holds the matching 192 KB slice of hidden_weight in SMEM (transposed,
// k fastest, stride 260). h and r*h (4 rows) live k-major [k][4] so one
// LDS.128 feeds f32x2 row-pairs. Cluster-wide exchange of r*h and h_new
// slices via DSMEM; 2 cluster.syncs/step.
// ---------------------------------------------------------------------------
#define W1_FL (128 * 260)
#define W2_FL (64 * 260)
#define RNN_SMEM_FL (W1_FL + W2_FL + 1024 + 1024 + 256 + 2048)

__global__ void __launch_bounds__(512, 1) __cluster_dims__(4, 1, 1)
rnn_kernel(const float* __restrict__ Wh, float* __restrict__ out) {
    extern __shared__ float smem[];
    float* W1T = smem;                 // [128][260]  r-cols 0..63, u-cols 64..127
    float* W2T = W1T + W1_FL;          // [64][260]   cand cols
    float* h4  = W2T + W2_FL;          // [256][4]    k-major hidden state, 4 rows
    float* rh4 = h4 + 1024;            // [256][4]    k-major r*h
    float* uS  = rh4 + 1024;           // [4][64]     update gate slice
    float* red = uS + 256;             // [2048]      cross-K reduction scratch

    const int tid = threadIdx.x;
    uint32_t cr;
    asm("mov.u32 %0, %%cluster_ctarank;" : "=r"(cr));
    const int b0 = (blockIdx.x >> 2) * 4;   // cluster id * 4 batch rows

    // Load weight slices (one-time, coalesced gmem reads, k-transposed store)
    for (int idx = tid; idx < 128 * 256; idx += 512) {
        int c = idx & 127, k = idx >> 7;
        int gcol = (c < 64) ? ((int)cr * 64 + c) : (256 + (int)cr * 64 + (c - 64));
        W1T[c * 260 + k] = Wh[(size_t)k * GG + gcol];
    }
    for (int idx = tid; idx < 64 * 256; idx += 512) {
        int c = idx & 63, k = idx >> 6;
        W2T[c * 260 + k] = Wh[(size_t)k * GG + 512 + cr * 64 + c];
    }
    for (int i = tid; i < 1024; i += 512) h4[i] = 0.f;
    __syncthreads();
    CLUSTER_SYNC();

    // thread identities
    const int c1  = tid & 127;         // phase1 col (0..63 = r, 64..127 = u)
    const int kq  = tid >> 7;          // phase1 K-quarter; also finalize1 row
    const int c2  = tid & 63;          // phase2 col
    const int kq8 = tid >> 6;          // phase2 K-eighth
    const int r2  = (tid >> 6) & 3;    // finalize2 row (valid when tid<256)

    const int gcol1 = (c1 < 64) ? ((int)cr * 64 + c1) : (256 + (int)cr * 64 + (c1 - 64));
    const float* pre1p = g_Pre + (size_t)(b0 + kq) * TT * GG + gcol1;
    const float* pre2p = g_Pre + (size_t)(b0 + r2) * TT * GG + 512 + cr * 64 + c2;

    const uint32_t rh4_u32 = (uint32_t)__cvta_generic_to_shared(rh4);
    const uint32_t h4_u32  = (uint32_t)__cvta_generic_to_shared(h4);

    const float* wp1 = W1T + c1 * 260 + kq * 64;
    const float* hp1 = h4 + kq * 64 * 4;
    const float* wp2 = W2T + c2 * 260 + kq8 * 32;
    const float* rp2 = rh4 + kq8 * 32 * 4;

    for (int t = 0; t < TT; t++) {
        // prefetch pre-activations for this step (hidden under the k-loops)
        float p1 = pre1p[(size_t)t * GG];
        float p2 = 0.f;
        if (tid < 256) p2 = pre2p[(size_t)t * GG];

        // ---- phase 1: partial h @ [Whr|Whu] slice over this K-quarter ----
        unsigned long long a01 = 0ull, a23 = 0ull;
#pragma unroll 4
        for (int k = 0; k < 64; k += 4) {
            float4 wv = *reinterpret_cast<const float4*>(wp1 + k);
            ulonglong2 hA = *reinterpret_cast<const ulonglong2*>(hp1 + (k + 0) * 4);
            ulonglong2 hB = *reinterpret_cast<const ulonglong2*>(hp1 + (k + 1) * 4);
            ulonglong2 hC = *reinterpret_cast<const ulonglong2*>(hp1 + (k + 2) * 4);
            ulonglong2 hD = *reinterpret_cast<const ulonglong2*>(hp1 + (k + 3) * 4);
            unsigned long long w0, w1, w2, w3;
            PACK2(w0, wv.x, wv.x);
            PACK2(w1, wv.y, wv.y);
            PACK2(w2, wv.z, wv.z);
            PACK2(w3, wv.w, wv.w);
            FMA2(a01, w0, hA.x); FMA2(a23, w0, hA.y);
            FMA2(a01, w1, hB.x); FMA2(a23, w1, hB.y);
            FMA2(a01, w2, hC.x); FMA2(a23, w2, hC.y);
            FMA2(a01, w3, hD.x); FMA2(a23, w3, hD.y);
        }
        {
            ulonglong2 st; st.x = a01; st.y = a23;
            *reinterpret_cast<ulonglong2*>(red + (kq * 128 + c1) * 4) = st;
        }
        __syncthreads();

        // ---- finalize gates r, u (row = kq, col = c1) ----
        {
            float v = red[(0 * 128 + c1) * 4 + kq] + red[(1 * 128 + c1) * 4 + kq] +
                      red[(2 * 128 + c1) * 4 + kq] + red[(3 * 128 + c1) * 4 + kq] + p1;
            float sg = 1.f / (1.f + __expf(-v));
            if (c1 < 64) {
                int kidx = (int)cr * 64 + c1;
                float rh = sg * h4[kidx * 4 + kq];
                uint32_t off = rh4_u32 + (uint32_t)(kidx * 4 + kq) * 4u;
                dsmem_store(off, 0, rh);
                dsmem_store(off, 1, rh);
                dsmem_store(off, 2, rh);
                dsmem_store(off, 3, rh);
            } else {
                uS[kq * 64 + (c1 - 64)] = sg;
            }
        }
        CLUSTER_SYNC();   // all rh slices visible everywhere

        // ---- phase 2: partial (r*h) @ Whh slice over this K-eighth ----
        unsigned long long b01 = 0ull, b23 = 0ull;
#pragma unroll 4
        for (int k = 0; k < 32; k += 4) {
            float4 wv = *reinterpret_cast<const float4*>(wp2 + k);
            ulonglong2 hA = *reinterpret_cast<const ulonglong2*>(rp2 + (k + 0) * 4);
            ulonglong2 hB = *reinterpret_cast<const ulonglong2*>(rp2 + (k + 1) * 4);
            ulonglong2 hC = *reinterpret_cast<const ulonglong2*>(rp2 + (k + 2) * 4);
            ulonglong2 hD = *reinterpret_cast<const ulonglong2*>(rp2 + (k + 3) * 4);
            unsigned long long w0, w1, w2, w3;
            PACK2(w0, wv.x, wv.x);
            PACK2(w1, wv.y, wv.y);
            PACK2(w2, wv.z, wv.z);
            PACK2(w3, wv.w, wv.w);
            FMA2(b01, w0, hA.x); FMA2(b23, w0, hA.y);
            FMA2(b01, w1, hB.x); FMA2(b23, w1, hB.y);
            FMA2(b01, w2, hC.x); FMA2(b23, w2, hC.y);
            FMA2(b01, w3, hD.x); FMA2(b23, w3, hD.y);
        }
        {
            ulonglong2 st; st.x = b01; st.y = b23;
            *reinterpret_cast<ulonglong2*>(red + (kq8 * 64 + c2) * 4) = st;
        }
        __syncthreads();

        // ---- finalize cand + state update (256 items) ----
        if (tid < 256) {
            float v = p2;
#pragma unroll
            for (int q = 0; q < 8; q++) v += red[(q * 64 + c2) * 4 + r2];
            float av = fabsf(v);
            float e  = __expf(-2.f * av);
            float cand = copysignf((1.f - e) / (1.f + e), v);
            float u  = uS[r2 * 64 + c2];
            int kidx = (int)cr * 64 + c2;
            float hold = h4[kidx * 4 + r2];
            float hn = u * hold + (1.f - u) * cand;
            out[((size_t)(b0 + r2) * TT + t) * UU + kidx] = hn;
            uint32_t off = h4_u32 + (uint32_t)(kidx * 4 + r2) * 4u;
            dsmem_store(off, 0, hn);
            dsmem_store(off, 1, hn);
            dsmem_store(off, 2, hn);
            dsmem_store(off, 3, hn);
        }
        CLUSTER_SYNC();   // all h_new slices visible everywhere
    }
}

// ---------------------------------------------------------------------------
// Launch
// ---------------------------------------------------------------------------
extern "C" void kernel_launch(void* const* d_in, const int* in_sizes, int n_in,
                              void* d_out, int out_size) {
    const float* x    = (const float*)d_in[0];
    const float* iw   = (const float*)d_in[1];
    const float* hw   = (const float*)d_in[2];
    const float* bias = (const float*)d_in[3];
    float* out = (float*)d_out;

    combine_kernel<<<(KK3 * GG + 1023) / 1024, 1024>>>(iw);

    dim3 pgrid(BB * TT / 128, GG / 128);   // 1024 x 6
    pre_gemm_kernel<<<pgrid, 256>>>(x, bias);

    static int smem_set = 0;
    if (!smem_set) {
        cudaFuncSetAttribute(rnn_kernel, cudaFuncAttributeMaxDynamicSharedMemorySize,
                             RNN_SMEM_FL * 4);
        smem_set = 1;
    }
    // 128 CTAs = 32 clusters of 4 (grid counts CTAs, not clusters!)
    rnn_kernel<<<BB, 512, RNN_SMEM_FL * 4>>>(hw, out);
}

// round 5
// speedup vs baseline: 1.8643x; 1.1321x over previous
#include <cuda_runtime.h>
#include <cuda_bf16.h>
#include <math.h>
#include <stdint.h>

// Problem constants
#define BB   128     // batch
#define TT   1024    // seq
#define DD   128     // in_dim
#define UU   256     // units
#define GG   768     // 3*units (r|u|c)
#define KK3  384     // 3*in_dim (x_t | x_{t-1} | x_{t-2})
#define MTOT (BB * TT)

// ---------------------------------------------------------------------------
// PTX helpers (all baseline sm_90/sm_80 PTX — no arch-'a' features)
// ---------------------------------------------------------------------------
#define FMA2(acc, a, b) asm("fma.rn.f32x2 %0, %1, %2, %0;" : "+l"(acc) : "l"(a), "l"(b))
#define PACK2(d, lo, hi) asm("mov.b64 %0, {%1, %2};" : "=l"(d) : "f"(lo), "f"(hi))

#define CLUSTER_SYNC() do { \
    asm volatile("barrier.cluster.arrive.aligned;" ::: "memory"); \
    asm volatile("barrier.cluster.wait.aligned;" ::: "memory"); \
} while (0)

__device__ __forceinline__ void dsmem_store(uint32_t saddr, uint32_t rank, float v) {
    uint32_t remote;
    asm("mapa.shared::cluster.u32 %0, %1, %2;" : "=r"(remote) : "r"(saddr), "r"(rank));
    asm volatile("st.shared::cluster.f32 [%0], %1;" :: "r"(remote), "f"(v) : "memory");
}

// bf16 m16n8k16 MMA (HMMA on Blackwell; baseline PTX, works on compute_103)
#define MMA_BF16(d, a, b) \
    asm volatile("mma.sync.aligned.m16n8k16.row.col.f32.bf16.bf16.f32 " \
        "{%0,%1,%2,%3}, {%4,%5,%6,%7}, {%8,%9}, {%0,%1,%2,%3};" \
        : "+f"((d)[0]), "+f"((d)[1]), "+f"((d)[2]), "+f"((d)[3]) \
        : "r"((a)[0]), "r"((a)[1]), "r"((a)[2]), "r"((a)[3]), "r"((b)[0]), "r"((b)[1]))

// ---------------------------------------------------------------------------
// Scratch (device globals: no allocations allowed)
// ---------------------------------------------------------------------------
__device__ __nv_bfloat16 g_xhi[(size_t)MTOT * DD];     // 32 MB
__device__ __nv_bfloat16 g_xlo[(size_t)MTOT * DD];     // 32 MB
__device__ __nv_bfloat16 g_WThi[GG * KK3];             // combined weights, [col][k3] K-major
__device__ __nv_bfloat16 g_WTlo[GG * KK3];
__device__ float g_Pre[(size_t)BB * TT * GG];          // pre-activations (402 MB)

// ---------------------------------------------------------------------------
// Kernel 1: build combined input weights, K-major, bf16 hi/lo split.
//   coeff(x_t)=W+dW+ddW, coeff(x_{t-1})=-(dW+2ddW), coeff(x_{t-2})=ddW; cand: Wxh only.
// ---------------------------------------------------------------------------
__global__ void split_w_kernel(const float* __restrict__ iw) {
    int idx = blockIdx.x * blockDim.x + threadIdx.x;
    if (idx >= GG * KK3) return;
    int j  = idx / KK3;        // output col 0..767
    int k3 = idx - j * KK3;    // 0..383
    int gate = j >> 8;
    int ju   = j & 255;
    int s    = k3 >> 7;
    int k    = k3 & 127;
    const float* row = iw + (size_t)k * (7 * UU);
    float v = 0.f;
    if (gate == 0) {
        float W = row[0 * UU + ju], dW = row[3 * UU + ju], ddW = row[5 * UU + ju];
        v = (s == 0) ? (W + dW + ddW) : (s == 1) ? -(dW + 2.f * ddW) : ddW;
    } else if (gate == 1) {
        float W = row[1 * UU + ju], dW = row[4 * UU + ju], ddW = row[6 * UU + ju];
        v = (s == 0) ? (W + dW + ddW) : (s == 1) ? -(dW + 2.f * ddW) : ddW;
    } else {
        v = (s == 0) ? row[2 * UU + ju] : 0.f;
    }
    __nv_bfloat16 hi = __float2bfloat16_rn(v);
    __nv_bfloat16 lo = __float2bfloat16_rn(v - __bfloat162float(hi));
    g_WThi[idx] = hi;
    g_WTlo[idx] = lo;
}

// ---------------------------------------------------------------------------
// Kernel 2: split x into bf16 hi/lo (4 elems per thread).
// ---------------------------------------------------------------------------
__global__ void split_x_kernel(const float* __restrict__ x) {
    size_t i4 = (size_t)blockIdx.x * blockDim.x + threadIdx.x;   // < MTOT*DD/4
    float4 v = reinterpret_cast<const float4*>(x)[i4];
    __nv_bfloat16 h0 = __float2bfloat16_rn(v.x), h1 = __float2bfloat16_rn(v.y);
    __nv_bfloat16 h2 = __float2bfloat16_rn(v.z), h3 = __float2bfloat16_rn(v.w);
    __nv_bfloat16 l0 = __float2bfloat16_rn(v.x - __bfloat162float(h0));
    __nv_bfloat16 l1 = __float2bfloat16_rn(v.y - __bfloat162float(h1));
    __nv_bfloat16 l2 = __float2bfloat16_rn(v.z - __bfloat162float(h2));
    __nv_bfloat16 l3 = __float2bfloat16_rn(v.w - __bfloat162float(h3));
    __nv_bfloat16 hv[4] = {h0, h1, h2, h3};
    __nv_bfloat16 lv[4] = {l0, l1, l2, l3};
    reinterpret_cast<uint2*>(g_xhi)[i4] = *reinterpret_cast<uint2*>(hv);
    reinterpret_cast<uint2*>(g_xlo)[i4] = *reinterpret_cast<uint2*>(lv);
}

// ---------------------------------------------------------------------------
// Kernel 3: tensor precompute via mma.sync m16n8k16 bf16, 3-term split.
// Pre[m][j] = sum_k3 X3[m][k3]*W3[k3][j] + bias[j], X3 = x shifted by s=k3>>7.
// CTA: 256 threads, tile M=128 x N=128, K chunks of 128.
// Warps 4x2: warp m-strip 32 rows, n-strip 64 cols; frags loaded by explicit
// LDS from padded SMEM (row stride 136 bf16 = 272 B -> 4-bank rotation,
// conflict-free for the 8x(4-lane) fragment access pattern).
// ---------------------------------------------------------------------------
#define TS 136                         // SMEM row stride in bf16
#define TILE_FL (128 * TS)             // one tile: 17408 bf16 = 34816 B
#define MP_SMEM_BYTES (4 * TILE_FL * 2)

__device__ __forceinline__ void ld_tile_A(__nv_bfloat16* dst,
                                          const __nv_bfloat16* __restrict__ src,
                                          int m0, int s, int tid) {
#pragma unroll
    for (int i = 0; i < 8; i++) {
        int idx = tid + i * 256;          // 0..2047
        int r   = idx >> 4;               // row 0..127
        int c8  = (idx & 15) << 3;        // col 0,8,...,120
        int m   = m0 + r;
        uint4 val = make_uint4(0u, 0u, 0u, 0u);
        if ((m & (TT - 1)) >= s)
            val = *reinterpret_cast<const uint4*>(src + (size_t)(m - s) * DD + c8);
        *reinterpret_cast<uint4*>(dst + r * TS + c8) = val;
    }
}

__device__ __forceinline__ void ld_tile_B(__nv_bfloat16* dst,
                                          const __nv_bfloat16* __restrict__ src,
                                          int n0, int s, int tid) {
#pragma unroll
    for (int i = 0; i < 8; i++) {
        int idx = tid + i * 256;
        int r   = idx >> 4;
        int c8  = (idx & 15) << 3;
        uint4 val = *reinterpret_cast<const uint4*>(src + (size_t)(n0 + r) * KK3 + s * 128 + c8);
        *reinterpret_cast<uint4*>(dst + r * TS + c8) = val;
    }
}

__global__ void __launch_bounds__(256, 1) mma_pre_kernel(const float* __restrict__ bias) {
    extern __shared__ __nv_bfloat16 sm[];
    __nv_bfloat16* Ahi = sm;
    __nv_bfloat16* Alo = sm + TILE_FL;
    __nv_bfloat16* Bhi = sm + 2 * TILE_FL;
    __nv_bfloat16* Blo = sm + 3 * TILE_FL;

    const int tid  = threadIdx.x;
    const int wid  = tid >> 5;
    const int lane = tid & 31;
    const int wm   = wid & 3;          // m-strip: rows [wm*32, wm*32+32)
    const int wn   = wid >> 2;         // n-strip: cols [wn*64, wn*64+64)
    const int m0 = blockIdx.x * 128;
    const int n0 = blockIdx.y * 128;
    const int nchunks = (n0 < 512) ? 3 : 1;   // cand gate: only x_t (K=128)

    const int qa = (lane & 3) * 2;     // k sub-offset within fragment
    const int gp = lane >> 2;          // group id 0..7

    float acc[2][8][4];
#pragma unroll
    for (int mf = 0; mf < 2; mf++)
#pragma unroll
        for (int nf = 0; nf < 8; nf++)
#pragma unroll
            for (int q = 0; q < 4; q++) acc[mf][nf][q] = 0.f;

    for (int s = 0; s < nchunks; s++) {
        __syncthreads();               // previous chunk's compute done
        ld_tile_A(Ahi, g_xhi, m0, s, tid);
        ld_tile_A(Alo, g_xlo, m0, s, tid);
        ld_tile_B(Bhi, g_WThi, n0, s, tid);
        ld_tile_B(Blo, g_WTlo, n0, s, tid);
        __syncthreads();

#pragma unroll
        for (int ks = 0; ks < 8; ks++) {
            const int k0 = ks * 16;
            uint32_t ah[2][4], al[2][4];
#pragma unroll
            for (int mf = 0; mf < 2; mf++) {
                int r = wm * 32 + mf * 16 + gp;
                ah[mf][0] = *reinterpret_cast<const uint32_t*>(&Ahi[r * TS + k0 + qa]);
                ah[mf][1] = *reinterpret_cast<const uint32_t*>(&Ahi[(r + 8) * TS + k0 + qa]);
                ah[mf][2] = *reinterpret_cast<const uint32_t*>(&Ahi[r * TS + k0 + 8 + qa]);
                ah[mf][3] = *reinterpret_cast<const uint32_t*>(&Ahi[(r + 8) * TS + k0 + 8 + qa]);
                al[mf][0] = *reinterpret_cast<const uint32_t*>(&Alo[r * TS + k0 + qa]);
                al[mf][1] = *reinterpret_cast<const uint32_t*>(&Alo[(r + 8) * TS + k0 + qa]);
                al[mf][2] = *reinterpret_cast<const uint32_t*>(&Alo[r * TS + k0 + 8 + qa]);
                al[mf][3] = *reinterpret_cast<const uint32_t*>(&Alo[(r + 8) * TS + k0 + 8 + qa]);
            }
            uint32_t bh[8][2], bl[8][2];
#pragma unroll
            for (int nf = 0; nf < 8; nf++) {
                int n = wn * 64 + nf * 8 + gp;
                bh[nf][0] = *reinterpret_cast<const uint32_t*>(&Bhi[n * TS + k0 + qa]);
                bh[nf][1] = *reinterpret_cast<const uint32_t*>(&Bhi[n * TS + k0 + 8 + qa]);
                bl[nf][0] = *reinterpret_cast<const uint32_t*>(&Blo[n * TS + k0 + qa]);
                bl[nf][1] = *reinterpret_cast<const uint32_t*>(&Blo[n * TS + k0 + 8 + qa]);
            }
#pragma unroll
            for (int mf = 0; mf < 2; mf++)
#pragma unroll
                for (int nf = 0; nf < 8; nf++) {
                    MMA_BF16(acc[mf][nf], ah[mf], bh[nf]);
                    MMA_BF16(acc[mf][nf], ah[mf], bl[nf]);
                    MMA_BF16(acc[mf][nf], al[mf], bh[nf]);
                }
        }
    }

    // Epilogue: c0,c1 -> row=gp, cols qa..qa+1; c2,c3 -> row=gp+8.
#pragma unroll
    for (int nf = 0; nf < 8; nf++) {
        int col = n0 + wn * 64 + nf * 8 + qa;
        float2 bz = *reinterpret_cast<const float2*>(bias + col);
#pragma unroll
        for (int mf = 0; mf < 2; mf++) {
            int row = m0 + wm * 32 + mf * 16 + gp;
            float2 v0, v1;
            v0.x = acc[mf][nf][0] + bz.x;
            v0.y = acc[mf][nf][1] + bz.y;
            v1.x = acc[mf][nf][2] + bz.x;
            v1.y = acc[mf][nf][3] + bz.y;
            *reinterpret_cast<float2*>(&g_Pre[(size_t)row * GG + col]) = v0;
            *reinterpret_cast<float2*>(&g_Pre[(size_t)(row + 8) * GG + col]) = v1;
        }
    }
}

// ---------------------------------------------------------------------------
// Kernel 4: recurrence (unchanged from round 3 — proven).
// ---------------------------------------------------------------------------
#define W1_FL (128 * 260)
#define W2_FL (64 * 260)
#define RNN_SMEM_FL (W1_FL + W2_FL + 1024 + 1024 + 256 + 2048)

__global__ void __launch_bounds__(512, 1) __cluster_dims__(4, 1, 1)
rnn_kernel(const float* __restrict__ Wh, float* __restrict__ out) {
    extern __shared__ float smemf[];
    float* W1T = smemf;
    float* W2T = W1T + W1_FL;
    float* h4  = W2T + W2_FL;
    float* rh4 = h4 + 1024;
    float* uS  = rh4 + 1024;
    float* red = uS + 256;

    const int tid = threadIdx.x;
    uint32_t cr;
    asm("mov.u32 %0, %%cluster_ctarank;" : "=r"(cr));
    const int b0 = (blockIdx.x >> 2) * 4;

    for (int idx = tid; idx < 128 * 256; idx += 512) {
        int c = idx & 127, k = idx >> 7;
        int gcol = (c < 64) ? ((int)cr * 64 + c) : (256 + (int)cr * 64 + (c - 64));
        W1T[c * 260 + k] = Wh[(size_t)k * GG + gcol];
    }
    for (int idx = tid; idx < 64 * 256; idx += 512) {
        int c = idx & 63, k = idx >> 6;
        W2T[c * 260 + k] = Wh[(size_t)k * GG + 512 + cr * 64 + c];
    }
    for (int i = tid; i < 1024; i += 512) h4[i] = 0.f;
    __syncthreads();
    CLUSTER_SYNC();

    const int c1  = tid & 127;
    const int kq  = tid >> 7;
    const int c2  = tid & 63;
    const int kq8 = tid >> 6;
    const int r2  = (tid >> 6) & 3;

    const int gcol1 = (c1 < 64) ? ((int)cr * 64 + c1) : (256 + (int)cr * 64 + (c1 - 64));
    const float* pre1p = g_Pre + (size_t)(b0 + kq) * TT * GG + gcol1;
    const float* pre2p = g_Pre + (size_t)(b0 + r2) * TT * GG + 512 + cr * 64 + c2;

    const uint32_t rh4_u32 = (uint32_t)__cvta_generic_to_shared(rh4);
    const uint32_t h4_u32  = (uint32_t)__cvta_generic_to_shared(h4);

    const float* wp1 = W1T + c1 * 260 + kq * 64;
    const float* hp1 = h4 + kq * 64 * 4;
    const float* wp2 = W2T + c2 * 260 + kq8 * 32;
    const float* rp2 = rh4 + kq8 * 32 * 4;

    for (int t = 0; t < TT; t++) {
        float p1 = pre1p[(size_t)t * GG];
        float p2 = 0.f;
        if (tid < 256) p2 = pre2p[(size_t)t * GG];

        unsigned long long a01 = 0ull, a23 = 0ull;
#pragma unroll 4
        for (int k = 0; k < 64; k += 4) {
            float4 wv = *reinterpret_cast<const float4*>(wp1 + k);
            ulonglong2 hA = *reinterpret_cast<const ulonglong2*>(hp1 + (k + 0) * 4);
            ulonglong2 hB = *reinterpret_cast<const ulonglong2*>(hp1 + (k + 1) * 4);
            ulonglong2 hC = *reinterpret_cast<const ulonglong2*>(hp1 + (k + 2) * 4);
            ulonglong2 hD = *reinterpret_cast<const ulonglong2*>(hp1 + (k + 3) * 4);
            unsigned long long w0, w1, w2, w3;
            PACK2(w0, wv.x, wv.x);
            PACK2(w1, wv.y, wv.y);
            PACK2(w2, wv.z, wv.z);
            PACK2(w3, wv.w, wv.w);
            FMA2(a01, w0, hA.x); FMA2(a23, w0, hA.y);
            FMA2(a01, w1, hB.x); FMA2(a23, w1, hB.y);
            FMA2(a01, w2, hC.x); FMA2(a23, w2, hC.y);
            FMA2(a01, w3, hD.x); FMA2(a23, w3, hD.y);
        }
        {
            ulonglong2 st; st.x = a01; st.y = a23;
            *reinterpret_cast<ulonglong2*>(red + (kq * 128 + c1) * 4) = st;
        }
        __syncthreads();

        {
            float v = red[(0 * 128 + c1) * 4 + kq] + red[(1 * 128 + c1) * 4 + kq] +
                      red[(2 * 128 + c1) * 4 + kq] + red[(3 * 128 + c1) * 4 + kq] + p1;
            float sg = 1.f / (1.f + __expf(-v));
            if (c1 < 64) {
                int kidx = (int)cr * 64 + c1;
                float rh = sg * h4[kidx * 4 + kq];
                uint32_t off = rh4_u32 + (uint32_t)(kidx * 4 + kq) * 4u;
                dsmem_store(off, 0, rh);
                dsmem_store(off, 1, rh);
                dsmem_store(off, 2, rh);
                dsmem_store(off, 3, rh);
            } else {
                uS[kq * 64 + (c1 - 64)] = sg;
            }
        }
        CLUSTER_SYNC();

        unsigned long long b01 = 0ull, b23 = 0ull;
#pragma unroll 4
        for (int k = 0; k < 32; k += 4) {
            float4 wv = *reinterpret_cast<const float4*>(wp2 + k);
            ulonglong2 hA = *reinterpret_cast<const ulonglong2*>(rp2 + (k + 0) * 4);
            ulonglong2 hB = *reinterpret_cast<const ulonglong2*>(rp2 + (k + 1) * 4);
            ulonglong2 hC = *reinterpret_cast<const ulonglong2*>(rp2 + (k + 2) * 4);
            ulonglong2 hD = *reinterpret_cast<const ulonglong2*>(rp2 + (k + 3) * 4);
            unsigned long long w0, w1, w2, w3;
            PACK2(w0, wv.x, wv.x);
            PACK2(w1, wv.y, wv.y);
            PACK2(w2, wv.z, wv.z);
            PACK2(w3, wv.w, wv.w);
            FMA2(b01, w0, hA.x); FMA2(b23, w0, hA.y);
            FMA2(b01, w1, hB.x); FMA2(b23, w1, hB.y);
            FMA2(b01, w2, hC.x); FMA2(b23, w2, hC.y);
            FMA2(b01, w3, hD.x); FMA2(b23, w3, hD.y);
        }
        {
            ulonglong2 st; st.x = b01; st.y = b23;
            *reinterpret_cast<ulonglong2*>(red + (kq8 * 64 + c2) * 4) = st;
        }
        __syncthreads();

        if (tid < 256) {
            float v = p2;
#pragma unroll
            for (int q = 0; q < 8; q++) v += red[(q * 64 + c2) * 4 + r2];
            float av = fabsf(v);
            float e  = __expf(-2.f * av);
            float cand = copysignf((1.f - e) / (1.f + e), v);
            float u  = uS[r2 * 64 + c2];
            int kidx = (int)cr * 64 + c2;
            float hold = h4[kidx * 4 + r2];
            float hn = u * hold + (1.f - u) * cand;
            out[((size_t)(b0 + r2) * TT + t) * UU + kidx] = hn;
            uint32_t off = h4_u32 + (uint32_t)(kidx * 4 + r2) * 4u;
            dsmem_store(off, 0, hn);
            dsmem_store(off, 1, hn);
            dsmem_store(off, 2, hn);
            dsmem_store(off, 3, hn);
        }
        CLUSTER_SYNC();
    }
}

// ---------------------------------------------------------------------------
// Launch
// ---------------------------------------------------------------------------
extern "C" void kernel_launch(void* const* d_in, const int* in_sizes, int n_in,
                              void* d_out, int out_size) {
    const float* x    = (const float*)d_in[0];
    const float* iw   = (const float*)d_in[1];
    const float* hw   = (const float*)d_in[2];
    const float* bias = (const float*)d_in[3];
    float* out = (float*)d_out;

    static int attr_set = 0;
    if (!attr_set) {
        cudaFuncSetAttribute(mma_pre_kernel, cudaFuncAttributeMaxDynamicSharedMemorySize,
                             MP_SMEM_BYTES);
        cudaFuncSetAttribute(rnn_kernel, cudaFuncAttributeMaxDynamicSharedMemorySize,
                             RNN_SMEM_FL * 4);
        attr_set = 1;
    }

    split_w_kernel<<<(GG * KK3 + 255) / 256, 256>>>(iw);
    split_x_kernel<<<(MTOT * DD / 4) / 256, 256>>>(x);

    dim3 pgrid(MTOT / 128, GG / 128);   // 1024 x 6
    mma_pre_kernel<<<pgrid, 256, MP_SMEM_BYTES>>>(bias);

    // 128 CTAs = 32 clusters of 4
    rnn_kernel<<<BB, 512, RNN_SMEM_FL * 4>>>(hw, out);
}

// round 6
// speedup vs baseline: 2.3648x; 1.2684x over previous
#include <cuda_runtime.h>
#include <cuda_bf16.h>
#include <math.h>
#include <stdint.h>

// Problem constants
#define BB   128     // batch
#define TT   1024    // seq
#define DD   128     // in_dim
#define UU   256     // units
#define GG   768     // 3*units (r|u|c)
#define KK3  384     // 3*in_dim (x_t | x_{t-1} | x_{t-2})
#define MTOT (BB * TT)

// ---------------------------------------------------------------------------
// PTX helpers (baseline PTX only — no sm_103a-only features)
// ---------------------------------------------------------------------------
#define CLUSTER_SYNC() do { \
    asm volatile("barrier.cluster.arrive.aligned;" ::: "memory"); \
    asm volatile("barrier.cluster.wait.aligned;" ::: "memory"); \
} while (0)

__device__ __forceinline__ void st_cluster_u32(uint32_t addr, uint32_t v) {
    asm volatile("st.shared::cluster.u32 [%0], %1;" :: "r"(addr), "r"(v) : "memory");
}

// bf16 m16n8k16 MMA (fragment layouts verified by the passing round-5 kernel)
#define MMA_BF16(d, a, b) \
    asm volatile("mma.sync.aligned.m16n8k16.row.col.f32.bf16.bf16.f32 " \
        "{%0,%1,%2,%3}, {%4,%5,%6,%7}, {%8,%9}, {%0,%1,%2,%3};" \
        : "+f"((d)[0]), "+f"((d)[1]), "+f"((d)[2]), "+f"((d)[3]) \
        : "r"((a)[0]), "r"((a)[1]), "r"((a)[2]), "r"((a)[3]), "r"((b)[0]), "r"((b)[1]))

// split (a,b) fp32 pair into packed bf16x2 hi and lo words (low half = a)
__device__ __forceinline__ void split_pack(float a, float b, uint32_t& hi, uint32_t& lo) {
    __nv_bfloat16 ah = __float2bfloat16_rn(a), bh = __float2bfloat16_rn(b);
    __nv_bfloat16 al = __float2bfloat16_rn(a - __bfloat162float(ah));
    __nv_bfloat16 bl = __float2bfloat16_rn(b - __bfloat162float(bh));
    __nv_bfloat162 h2; h2.x = ah; h2.y = bh;
    __nv_bfloat162 l2; l2.x = al; l2.y = bl;
    hi = *reinterpret_cast<uint32_t*>(&h2);
    lo = *reinterpret_cast<uint32_t*>(&l2);
}

// ---------------------------------------------------------------------------
// Scratch (device globals: no allocations allowed)
// ---------------------------------------------------------------------------
__device__ __nv_bfloat16 g_xhi[(size_t)MTOT * DD];     // 32 MB
__device__ __nv_bfloat16 g_xlo[(size_t)MTOT * DD];     // 32 MB
__device__ __nv_bfloat16 g_WThi[GG * KK3];             // combined weights, [col][k3] K-major
__device__ __nv_bfloat16 g_WTlo[GG * KK3];
__device__ float g_Pre[(size_t)BB * TT * GG];          // pre-activations (402 MB)

// ---------------------------------------------------------------------------
// Kernel 1: build combined input weights, K-major, bf16 hi/lo split.
//   coeff(x_t)=W+dW+ddW, coeff(x_{t-1})=-(dW+2ddW), coeff(x_{t-2})=ddW; cand: Wxh only.
// ---------------------------------------------------------------------------
__global__ void split_w_kernel(const float* __restrict__ iw) {
    int idx = blockIdx.x * blockDim.x + threadIdx.x;
    if (idx >= GG * KK3) return;
    int j  = idx / KK3;
    int k3 = idx - j * KK3;
    int gate = j >> 8;
    int ju   = j & 255;
    int s    = k3 >> 7;
    int k    = k3 & 127;
    const float* row = iw + (size_t)k * (7 * UU);
    float v = 0.f;
    if (gate == 0) {
        float W = row[0 * UU + ju], dW = row[3 * UU + ju], ddW = row[5 * UU + ju];
        v = (s == 0) ? (W + dW + ddW) : (s == 1) ? -(dW + 2.f * ddW) : ddW;
    } else if (gate == 1) {
        float W = row[1 * UU + ju], dW = row[4 * UU + ju], ddW = row[6 * UU + ju];
        v = (s == 0) ? (W + dW + ddW) : (s == 1) ? -(dW + 2.f * ddW) : ddW;
    } else {
        v = (s == 0) ? row[2 * UU + ju] : 0.f;
    }
    __nv_bfloat16 hi = __float2bfloat16_rn(v);
    __nv_bfloat16 lo = __float2bfloat16_rn(v - __bfloat162float(hi));
    g_WThi[idx] = hi;
    g_WTlo[idx] = lo;
}

// ---------------------------------------------------------------------------
// Kernel 2: split x into bf16 hi/lo (4 elems per thread).
// ---------------------------------------------------------------------------
__global__ void split_x_kernel(const float* __restrict__ x) {
    size_t i4 = (size_t)blockIdx.x * blockDim.x + threadIdx.x;
    float4 v = reinterpret_cast<const float4*>(x)[i4];
    __nv_bfloat16 h0 = __float2bfloat16_rn(v.x), h1 = __float2bfloat16_rn(v.y);
    __nv_bfloat16 h2 = __float2bfloat16_rn(v.z), h3 = __float2bfloat16_rn(v.w);
    __nv_bfloat16 l0 = __float2bfloat16_rn(v.x - __bfloat162float(h0));
    __nv_bfloat16 l1 = __float2bfloat16_rn(v.y - __bfloat162float(h1));
    __nv_bfloat16 l2 = __float2bfloat16_rn(v.z - __bfloat162float(h2));
    __nv_bfloat16 l3 = __float2bfloat16_rn(v.w - __bfloat162float(h3));
    __nv_bfloat16 hv[4] = {h0, h1, h2, h3};
    __nv_bfloat16 lv[4] = {l0, l1, l2, l3};
    reinterpret_cast<uint2*>(g_xhi)[i4] = *reinterpret_cast<uint2*>(hv);
    reinterpret_cast<uint2*>(g_xlo)[i4] = *reinterpret_cast<uint2*>(lv);
}

// ---------------------------------------------------------------------------
// Kernel 3: tensor precompute via mma.sync m16n8k16 bf16 (unchanged, proven).
// ---------------------------------------------------------------------------
#define TS 136
#define TILE_FL (128 * TS)
#define MP_SMEM_BYTES (4 * TILE_FL * 2)

__device__ __forceinline__ void ld_tile_A(__nv_bfloat16* dst,
                                          const __nv_bfloat16* __restrict__ src,
                                          int m0, int s, int tid) {
#pragma unroll
    for (int i = 0; i < 8; i++) {
        int idx = tid + i * 256;
        int r   = idx >> 4;
        int c8  = (idx & 15) << 3;
        int m   = m0 + r;
        uint4 val = make_uint4(0u, 0u, 0u, 0u);
        if ((m & (TT - 1)) >= s)
            val = *reinterpret_cast<const uint4*>(src + (size_t)(m - s) * DD + c8);
        *reinterpret_cast<uint4*>(dst + r * TS + c8) = val;
    }
}

__device__ __forceinline__ void ld_tile_B(__nv_bfloat16* dst,
                                          const __nv_bfloat16* __restrict__ src,
                                          int n0, int s, int tid) {
#pragma unroll
    for (int i = 0; i < 8; i++) {
        int idx = tid + i * 256;
        int r   = idx >> 4;
        int c8  = (idx & 15) << 3;
        uint4 val = *reinterpret_cast<const uint4*>(src + (size_t)(n0 + r) * KK3 + s * 128 + c8);
        *reinterpret_cast<uint4*>(dst + r * TS + c8) = val;
    }
}

__global__ void __launch_bounds__(256, 1) mma_pre_kernel(const float* __restrict__ bias) {
    extern __shared__ __nv_bfloat16 sm[];
    __nv_bfloat16* Ahi = sm;
    __nv_bfloat16* Alo = sm + TILE_FL;
    __nv_bfloat16* Bhi = sm + 2 * TILE_FL;
    __nv_bfloat16* Blo = sm + 3 * TILE_FL;

    const int tid  = threadIdx.x;
    const int wid  = tid >> 5;
    const int lane = tid & 31;
    const int wm   = wid & 3;
    const int wn   = wid >> 2;
    const int m0 = blockIdx.x * 128;
    const int n0 = blockIdx.y * 128;
    const int nchunks = (n0 < 512) ? 3 : 1;

    const int qa = (lane & 3) * 2;
    const int gp = lane >> 2;

    float acc[2][8][4];
#pragma unroll
    for (int mf = 0; mf < 2; mf++)
#pragma unroll
        for (int nf = 0; nf < 8; nf++)
#pragma unroll
            for (int q = 0; q < 4; q++) acc[mf][nf][q] = 0.f;

    for (int s = 0; s < nchunks; s++) {
        __syncthreads();
        ld_tile_A(Ahi, g_xhi, m0, s, tid);
        ld_tile_A(Alo, g_xlo, m0, s, tid);
        ld_tile_B(Bhi, g_WThi, n0, s, tid);
        ld_tile_B(Blo, g_WTlo, n0, s, tid);
        __syncthreads();

#pragma unroll
        for (int ks = 0; ks < 8; ks++) {
            const int k0 = ks * 16;
            uint32_t ah[2][4], al[2][4];
#pragma unroll
            for (int mf = 0; mf < 2; mf++) {
                int r = wm * 32 + mf * 16 + gp;
                ah[mf][0] = *reinterpret_cast<const uint32_t*>(&Ahi[r * TS + k0 + qa]);
                ah[mf][1] = *reinterpret_cast<const uint32_t*>(&Ahi[(r + 8) * TS + k0 + qa]);
                ah[mf][2] = *reinterpret_cast<const uint32_t*>(&Ahi[r * TS + k0 + 8 + qa]);
                ah[mf][3] = *reinterpret_cast<const uint32_t*>(&Ahi[(r + 8) * TS + k0 + 8 + qa]);
                al[mf][0] = *reinterpret_cast<const uint32_t*>(&Alo[r * TS + k0 + qa]);
                al[mf][1] = *reinterpret_cast<const uint32_t*>(&Alo[(r + 8) * TS + k0 + qa]);
                al[mf][2] = *reinterpret_cast<const uint32_t*>(&Alo[r * TS + k0 + 8 + qa]);
                al[mf][3] = *reinterpret_cast<const uint32_t*>(&Alo[(r + 8) * TS + k0 + 8 + qa]);
            }
            uint32_t bh[8][2], bl[8][2];
#pragma unroll
            for (int nf = 0; nf < 8; nf++) {
                int n = wn * 64 + nf * 8 + gp;
                bh[nf][0] = *reinterpret_cast<const uint32_t*>(&Bhi[n * TS + k0 + qa]);
                bh[nf][1] = *reinterpret_cast<const uint32_t*>(&Bhi[n * TS + k0 + 8 + qa]);
                bl[nf][0] = *reinterpret_cast<const uint32_t*>(&Blo[n * TS + k0 + qa]);
                bl[nf][1] = *reinterpret_cast<const uint32_t*>(&Blo[n * TS + k0 + 8 + qa]);
            }
#pragma unroll
            for (int mf = 0; mf < 2; mf++)
#pragma unroll
                for (int nf = 0; nf < 8; nf++) {
                    MMA_BF16(acc[mf][nf], ah[mf], bh[nf]);
                    MMA_BF16(acc[mf][nf], ah[mf], bl[nf]);
                    MMA_BF16(acc[mf][nf], al[mf], bh[nf]);
                }
        }
    }

#pragma unroll
    for (int nf = 0; nf < 8; nf++) {
        int col = n0 + wn * 64 + nf * 8 + qa;
        float2 bz = *reinterpret_cast<const float2*>(bias + col);
#pragma unroll
        for (int mf = 0; mf < 2; mf++) {
            int row = m0 + wm * 32 + mf * 16 + gp;
            float2 v0, v1;
            v0.x = acc[mf][nf][0] + bz.x;
            v0.y = acc[mf][nf][1] + bz.y;
            v1.x = acc[mf][nf][2] + bz.x;
            v1.y = acc[mf][nf][3] + bz.y;
            *reinterpret_cast<float2*>(&g_Pre[(size_t)row * GG + col]) = v0;
            *reinterpret_cast<float2*>(&g_Pre[(size_t)(row + 8) * GG + col]) = v1;
        }
    }
}

// ---------------------------------------------------------------------------
// Kernel 4: HMMA recurrence, weights register-resident as bf16 hi/lo B-frags.
// Cluster of 4 CTAs, 4 batch rows/cluster; CTA rank cr owns cols
// [cr*64,(cr+1)*64) of each gate. A trick: A rows 0-3 = h_hi, rows 4-7 = h_lo
// (rows 8-15 zero) => A@B_hi + A@B_lo, then c[r]+c[r+4] gives the EXACT
// (h_hi+h_lo)@(W_hi+W_lo) product.
//   hAp/rhAp layout: u32 word = (val[2j], val[2j+1]) bf16 pair, word index
//   (j)*8 + row, rows 0-3 = hi, 4-7 = lo. A-frag a0 = hAp[(k0/2+tg)*8+gp],
//   a2 = hAp[(k0/2+tg+4)*8+gp]  (conflict-free: tg*8+gp covers 32 banks).
// Phase1: 16 warps = 16 n8-strips over 128 (r|u) cols, full K=256.
// Phase2: 16 warps = 8 n8-strips (cand) x 2 K-halves, SMEM reduction.
// Cluster exchange: rh and h_new bf16 hi/lo words via st.shared::cluster.
// ---------------------------------------------------------------------------
__global__ void __launch_bounds__(512, 1) __cluster_dims__(4, 1, 1)
rnn_kernel(const float* __restrict__ Wh, float* __restrict__ out) {
    __shared__ uint32_t hAp[1024];    // [128 pairs][8 rows]
    __shared__ uint32_t rhAp[1024];
    __shared__ float h4f[1024];       // [unit][row] fp32 hidden state
    __shared__ float uS[256];         // [row][col] update gate slice
    __shared__ float red[512];        // [kh][row][col] phase2 reduction

    const int tid  = threadIdx.x;
    const int w    = tid >> 5;
    const int lane = tid & 31;
    const int gp   = lane >> 2;
    const int tg   = lane & 3;
    const int qa   = tg * 2;
    uint32_t cr;
    asm("mov.u32 %0, %%cluster_ctarank;" : "=r"(cr));
    const int b0 = (blockIdx.x >> 2) * 4;

    // ---- one-time: load weight fragments into registers (bf16 hi/lo) ----
    uint32_t b1h[16][2], b1l[16][2];
    {
        int gcol = (w < 8) ? ((int)cr * 64 + w * 8 + gp)
                           : (256 + (int)cr * 64 + (w - 8) * 8 + gp);
#pragma unroll
        for (int ch = 0; ch < 16; ch++) {
            int k0 = ch * 16;
            float v00 = Wh[(size_t)(k0 + qa) * GG + gcol];
            float v01 = Wh[(size_t)(k0 + qa + 1) * GG + gcol];
            float v10 = Wh[(size_t)(k0 + 8 + qa) * GG + gcol];
            float v11 = Wh[(size_t)(k0 + 8 + qa + 1) * GG + gcol];
            split_pack(v00, v01, b1h[ch][0], b1l[ch][0]);
            split_pack(v10, v11, b1h[ch][1], b1l[ch][1]);
        }
    }
    const int ns = w & 7, kh = w >> 3;
    uint32_t b2h[8][2], b2l[8][2];
    {
        int gcol = 512 + (int)cr * 64 + ns * 8 + gp;
#pragma unroll
        for (int ch = 0; ch < 8; ch++) {
            int k0 = kh * 128 + ch * 16;
            float v00 = Wh[(size_t)(k0 + qa) * GG + gcol];
            float v01 = Wh[(size_t)(k0 + qa + 1) * GG + gcol];
            float v10 = Wh[(size_t)(k0 + 8 + qa) * GG + gcol];
            float v11 = Wh[(size_t)(k0 + 8 + qa + 1) * GG + gcol];
            split_pack(v00, v01, b2h[ch][0], b2l[ch][0]);
            split_pack(v10, v11, b2h[ch][1], b2l[ch][1]);
        }
    }

    // ---- init state + remote bases ----
    for (int i = tid; i < 1024; i += 512) { hAp[i] = 0u; h4f[i] = 0.f; }
    uint32_t remote_rh[4], remote_hA[4];
    {
        uint32_t rh_base = (uint32_t)__cvta_generic_to_shared(rhAp);
        uint32_t hA_base = (uint32_t)__cvta_generic_to_shared(hAp);
#pragma unroll
        for (int rr = 0; rr < 4; rr++) {
            asm("mapa.shared::cluster.u32 %0, %1, %2;" : "=r"(remote_rh[rr]) : "r"(rh_base), "r"(rr));
            asm("mapa.shared::cluster.u32 %0, %1, %2;" : "=r"(remote_hA[rr]) : "r"(hA_base), "r"(rr));
        }
    }
    __syncthreads();
    CLUSTER_SYNC();

    // finalize-2 identities
    const int r2 = (tid >> 6) & 3;
    const int c2 = tid & 63;
    const float* p2ptr = g_Pre + (size_t)(b0 + r2) * TT * GG + 512 + cr * 64 + c2;
    float* outp = out + ((size_t)(b0 + r2) * TT) * UU + cr * 64 + c2;

    // phase-1 p1 pointer (rows gp<4 use it)
    const int colbase1 = (w < 8) ? ((int)cr * 64 + w * 8 + qa)
                                 : (256 + (int)cr * 64 + (w - 8) * 8 + qa);
    const float* p1ptr = g_Pre + (size_t)(b0 + (gp & 3)) * TT * GG + colbase1;

    for (int t = 0; t < TT; t++) {
        float2 p1 = make_float2(0.f, 0.f);
        if (gp < 4) p1 = *reinterpret_cast<const float2*>(p1ptr + (size_t)t * GG);
        float p2 = 0.f;
        if (tid < 256) p2 = p2ptr[(size_t)t * GG];

        // ---- phase 1: h @ [Whr|Whu] strip (exact via hi/lo rows) ----
        float c[4] = {0.f, 0.f, 0.f, 0.f};
#pragma unroll
        for (int ch = 0; ch < 16; ch++) {
            uint32_t a[4];
            a[0] = hAp[(ch * 8 + tg) * 8 + gp];
            a[2] = hAp[(ch * 8 + tg + 4) * 8 + gp];
            a[1] = 0u; a[3] = 0u;
            MMA_BF16(c, a, b1h[ch]);
            MMA_BF16(c, a, b1l[ch]);
        }
        float v0 = c[0] + __shfl_down_sync(0xffffffffu, c[0], 16);
        float v1 = c[1] + __shfl_down_sync(0xffffffffu, c[1], 16);
        if (gp < 4) {
            v0 += p1.x; v1 += p1.y;
            float sg0 = 1.f / (1.f + __expf(-v0));
            float sg1 = 1.f / (1.f + __expf(-v1));
            if (w < 8) {   // r-gate: produce rh slice, broadcast to cluster
                int u0 = (int)cr * 64 + w * 8 + qa;
                float rh0 = sg0 * h4f[u0 * 4 + gp];
                float rh1 = sg1 * h4f[(u0 + 1) * 4 + gp];
                uint32_t whi, wlo;
                split_pack(rh0, rh1, whi, wlo);
                uint32_t offh = (uint32_t)(((u0 >> 1) * 8 + gp) * 4);
                uint32_t offl = (uint32_t)(((u0 >> 1) * 8 + gp + 4) * 4);
#pragma unroll
                for (int rr = 0; rr < 4; rr++) {
                    st_cluster_u32(remote_rh[rr] + offh, whi);
                    st_cluster_u32(remote_rh[rr] + offl, wlo);
                }
            } else {       // u-gate: local
                *reinterpret_cast<float2*>(&uS[gp * 64 + (w - 8) * 8 + qa]) =
                    make_float2(sg0, sg1);
            }
        }
        CLUSTER_SYNC();   // rh slices visible cluster-wide

        // ---- phase 2: (r*h) @ Whh strip over K-half ----
        float d[4] = {0.f, 0.f, 0.f, 0.f};
#pragma unroll
        for (int ch = 0; ch < 8; ch++) {
            uint32_t a[4];
            a[0] = rhAp[(kh * 64 + ch * 8 + tg) * 8 + gp];
            a[2] = rhAp[(kh * 64 + ch * 8 + tg + 4) * 8 + gp];
            a[1] = 0u; a[3] = 0u;
            MMA_BF16(d, a, b2h[ch]);
            MMA_BF16(d, a, b2l[ch]);
        }
        float y0 = d[0] + __shfl_down_sync(0xffffffffu, d[0], 16);
        float y1 = d[1] + __shfl_down_sync(0xffffffffu, d[1], 16);
        if (gp < 4)
            *reinterpret_cast<float2*>(&red[kh * 256 + gp * 64 + ns * 8 + qa]) =
                make_float2(y0, y1);
        __syncthreads();

        // ---- finalize: cand + state update + output + h exchange ----
        if (tid < 256) {
            float v = red[r2 * 64 + c2] + red[256 + r2 * 64 + c2] + p2;
            float av = fabsf(v), e = __expf(-2.f * av);
            float cand = copysignf((1.f - e) / (1.f + e), v);
            float u = uS[r2 * 64 + c2];
            int unit = (int)cr * 64 + c2;
            float hold = h4f[unit * 4 + r2];
            float hn = u * hold + (1.f - u) * cand;
            outp[(size_t)t * UU] = hn;
            h4f[unit * 4 + r2] = hn;
            float hn1 = __shfl_down_sync(0xffffffffu, hn, 1);
            if (!(c2 & 1)) {
                uint32_t whi, wlo;
                split_pack(hn, hn1, whi, wlo);
                uint32_t offh = (uint32_t)(((unit >> 1) * 8 + r2) * 4);
                uint32_t offl = (uint32_t)(((unit >> 1) * 8 + r2 + 4) * 4);
#pragma unroll
                for (int rr = 0; rr < 4; rr++) {
                    st_cluster_u32(remote_hA[rr] + offh, whi);
                    st_cluster_u32(remote_hA[rr] + offl, wlo);
                }
            }
        }
        CLUSTER_SYNC();   // h_new visible cluster-wide
    }
}

// ---------------------------------------------------------------------------
// Launch
// ---------------------------------------------------------------------------
extern "C" void kernel_launch(void* const* d_in, const int* in_sizes, int n_in,
                              void* d_out, int out_size) {
    const float* x    = (const float*)d_in[0];
    const float* iw   = (const float*)d_in[1];
    const float* hw   = (const float*)d_in[2];
    const float* bias = (const float*)d_in[3];
    float* out = (float*)d_out;

    static int attr_set = 0;
    if (!attr_set) {
        cudaFuncSetAttribute(mma_pre_kernel, cudaFuncAttributeMaxDynamicSharedMemorySize,
                             MP_SMEM_BYTES);
        attr_set = 1;
    }

    split_w_kernel<<<(GG * KK3 + 255) / 256, 256>>>(iw);
    split_x_kernel<<<(MTOT * DD / 4) / 256, 256>>>(x);

    dim3 pgrid(MTOT / 128, GG / 128);   // 1024 x 6
    mma_pre_kernel<<<pgrid, 256, MP_SMEM_BYTES>>>(bias);

    // 128 CTAs = 32 clusters of 4
    rnn_kernel<<<BB, 512>>>(hw, out);
}